// round 8
// baseline (speedup 1.0000x reference)
#include <cuda_runtime.h>
#include <cuda_bf16.h>

#define F_FEAT 16
#define D_IN   4
#define H      32
#define B_TOT  1024
#define T_MAX  512
#define NB     4          // batches per warp

typedef unsigned long long ull;

__device__ float g_hT[B_TOT * F_FEAT * H];      // [b][f][h]  == h_cat[b][f*H+h]
__device__ float g_WT[F_FEAT * H * H];          // W_sq transposed
__device__ int   g_perm[B_TOT];                 // batches sorted by len, descending

__device__ __forceinline__ float fast_sigmoid(float v) {
    return __fdividef(1.f, 1.f + __expf(-v));
}
__device__ __forceinline__ float fast_tanh(float a) {
    float e = __expf(-2.f * fabsf(a));
    float t = __fdividef(1.f - e, 1.f + e);
    return copysignf(t, a);
}
__device__ __forceinline__ ull pack2(float lo, float hi) {
    ull d; asm("mov.b64 %0, {%1, %2};" : "=l"(d) : "f"(lo), "f"(hi)); return d;
}
__device__ __forceinline__ void unpack2(ull v, float& lo, float& hi) {
    asm("mov.b64 {%0, %1}, %2;" : "=f"(lo), "=f"(hi) : "l"(v));
}
__device__ __forceinline__ ull fma2(ull a, ull b, ull c) {
    ull d; asm("fma.rn.f32x2 %0, %1, %2, %3;" : "=l"(d) : "l"(a), "l"(b), "l"(c)); return d;
}
__device__ __forceinline__ float hsum2(ull v) {
    float lo, hi; unpack2(v, lo, hi); return lo + hi;
}

// Rank-sort batches by length (descending, stable). O(B^2) but tiny (~5us).
__global__ void sort_lens(const int* __restrict__ lens) {
    int b = blockIdx.x * blockDim.x + threadIdx.x;
    if (b >= B_TOT) return;
    int L = lens[b];
    int r = 0;
    for (int j = 0; j < B_TOT; j++) {
        int Lj = __ldg(lens + j);
        r += (Lj < L) || (Lj == L && j < b);
    }
    g_perm[B_TOT - 1 - r] = b;   // descending: longest first
}

// One warp per (feature, group of NB=4 length-adjacent batches). All batches
// share the 96 weight registers; 12 independent fma2 chains per step; the
// serial tail (activations + STS/sync/LDS) is amortized over 4 batches.
__global__ void __launch_bounds__(128, 2) gru_kernel(
    const float* __restrict__ input,   // [B, F, T, D]
    const int*   __restrict__ lens,    // [B]
    const float* __restrict__ W_ih,    // [F, 3H, D]
    const float* __restrict__ W_hh,    // [F, 3H, H]
    const float* __restrict__ b_ih,    // [F, 3H]
    const float* __restrict__ b_hh)    // [F, 3H]
{
    __shared__ float hbuf[4][2][NB][H];   // [warp][buffer][batch-slot][k]

    const int lane  = threadIdx.x & 31;
    const int warp  = threadIdx.x >> 5;
    const int group = blockIdx.x;                // 0..255, longest groups first
    const int f     = blockIdx.y * 4 + warp;

    int bidx[NB], Lb[NB];
    #pragma unroll
    for (int n = 0; n < NB; n++) {
        bidx[n] = __ldg(g_perm + NB * group + n);
        Lb[n]   = __ldg(lens + bidx[n]);
    }
    const int L0 = Lb[0];                        // max (sorted descending)

    // --- recurrent weights, packed along k as (W[2q], W[2q+1]) pairs ---
    const float* Whh = W_hh + f * (3 * H) * H;
    ull Wr2[H/2], Wz2[H/2], Wn2[H/2];
    {
        const float4* r4 = (const float4*)(Whh + lane * H);
        const float4* z4 = (const float4*)(Whh + (H + lane) * H);
        const float4* n4 = (const float4*)(Whh + (2 * H + lane) * H);
        #pragma unroll
        for (int q = 0; q < H / 4; q++) {
            float4 a = __ldg(r4 + q);
            Wr2[2*q] = pack2(a.x, a.y);  Wr2[2*q+1] = pack2(a.z, a.w);
            float4 c = __ldg(z4 + q);
            Wz2[2*q] = pack2(c.x, c.y);  Wz2[2*q+1] = pack2(c.z, c.w);
            float4 d = __ldg(n4 + q);
            Wn2[2*q] = pack2(d.x, d.y);  Wn2[2*q+1] = pack2(d.z, d.w);
        }
    }

    // input weights, packed along d
    const float* Wih = W_ih + f * (3 * H) * D_IN;
    const float4 wir = __ldg((const float4*)Wih + lane);
    const float4 wiz = __ldg((const float4*)Wih + H + lane);
    const float4 win = __ldg((const float4*)Wih + 2 * H + lane);
    const ull Wir01 = pack2(wir.x, wir.y), Wir23 = pack2(wir.z, wir.w);
    const ull Wiz01 = pack2(wiz.x, wiz.y), Wiz23 = pack2(wiz.z, wiz.w);
    const ull Win01 = pack2(win.x, win.y), Win23 = pack2(win.z, win.w);

    const float br  = __ldg(b_ih + f * 3 * H + lane)     + __ldg(b_hh + f * 3 * H + lane);
    const float bz  = __ldg(b_ih + f * 3 * H + H + lane) + __ldg(b_hh + f * 3 * H + H + lane);
    const float bin = __ldg(b_ih + f * 3 * H + 2 * H + lane);
    const float bhn = __ldg(b_hh + f * 3 * H + 2 * H + lane);
    const ull  bias_r = pack2(br, 0.f), bias_z = pack2(bz, 0.f);
    const ull  bias_in = pack2(bin, 0.f), bias_hn = pack2(bhn, 0.f);

    const float4* xp[NB];
    #pragma unroll
    for (int n = 0; n < NB; n++)
        xp[n] = (const float4*)input + ((size_t)bidx[n] * F_FEAT + f) * T_MAX;

    float h[NB];
    #pragma unroll
    for (int n = 0; n < NB; n++) {
        h[n] = 0.f;
        hbuf[warp][0][n][lane] = 0.f;
    }
    __syncwarp();
    int p = 0;

    float4 x[NB];
    #pragma unroll
    for (int n = 0; n < NB; n++) x[n] = __ldg(xp[n]);   // L >= 1 always

    for (int t = 0; t < L0; t++) {
        // unconditional clamped prefetch (always in-bounds; clamped dup never used)
        const int tn = min(t + 1, L0 - 1);
        float4 xn[NB];
        #pragma unroll
        for (int n = 0; n < NB; n++) xn[n] = __ldg(xp[n] + tn);

        // input projections (pair-dots over d)
        ull gr2[NB], gz2[NB], gn2[NB], hn2[NB];
        #pragma unroll
        for (int n = 0; n < NB; n++) {
            const ull x01 = pack2(x[n].x, x[n].y);
            const ull x23 = pack2(x[n].z, x[n].w);
            gr2[n] = fma2(Wir23, x23, fma2(Wir01, x01, bias_r));
            gz2[n] = fma2(Wiz23, x23, fma2(Wiz01, x01, bias_z));
            gn2[n] = fma2(Win23, x23, fma2(Win01, x01, bias_in));
            hn2[n] = bias_hn;
        }

        // recurrent matvecs: 12 independent fma2 chains over k
        #pragma unroll
        for (int q = 0; q < H / 4; q++) {
            #pragma unroll
            for (int n = 0; n < NB; n++) {
                ulonglong2 hv = ((const ulonglong2*)&hbuf[warp][p][n][0])[q];  // LDS.128 broadcast
                gr2[n] = fma2(Wr2[2*q],   hv.x, gr2[n]);
                gz2[n] = fma2(Wz2[2*q],   hv.x, gz2[n]);
                hn2[n] = fma2(Wn2[2*q],   hv.x, hn2[n]);
                gr2[n] = fma2(Wr2[2*q+1], hv.y, gr2[n]);
                gz2[n] = fma2(Wz2[2*q+1], hv.y, gz2[n]);
                hn2[n] = fma2(Wn2[2*q+1], hv.y, hn2[n]);
            }
        }

        // activations: 4 independent tails, compiler-interleaved
        #pragma unroll
        for (int n = 0; n < NB; n++) {
            float r  = fast_sigmoid(hsum2(gr2[n]));
            float z  = fast_sigmoid(hsum2(gz2[n]));
            float nn = fast_tanh(fmaf(r, hsum2(hn2[n]), hsum2(gn2[n])));
            float hnew = fmaf(z, h[n] - nn, nn);      // (1-z)*n + z*h
            h[n] = (n == 0) ? hnew                    // slot 0: L0 == loop bound
                            : ((t < Lb[n]) ? hnew : h[n]);  // freeze past length
            hbuf[warp][p ^ 1][n][lane] = h[n];
        }
        __syncwarp();
        p ^= 1;
        #pragma unroll
        for (int n = 0; n < NB; n++) x[n] = xn[n];
    }

    #pragma unroll
    for (int n = 0; n < NB; n++)
        g_hT[((size_t)bidx[n] * F_FEAT + f) * H + lane] = h[n];
}

// Transpose W_sq [32][512] -> g_WT [512][32]
__global__ void transpose_wsq(const float* __restrict__ W_sq) {
    int i = blockIdx.x * blockDim.x + threadIdx.x;
    if (i < H * F_FEAT * H) {
        int r = i / (F_FEAT * H);
        int j = i % (F_FEAT * H);
        g_WT[j * H + r] = W_sq[i];
    }
}

// One warp per batch: h2 = relu(W_sq @ h_cat + b_sq); out = sigmoid(W_out @ h2 + b_out)
__global__ void head_kernel(
    const float* __restrict__ b_sq,
    const float* __restrict__ W_out,
    const float* __restrict__ b_out,
    float* __restrict__ out)
{
    const int lane = threadIdx.x & 31;
    const int b    = blockIdx.x * (blockDim.x >> 5) + (threadIdx.x >> 5);

    float acc = __ldg(b_sq + lane);
    const float* hb = g_hT + (size_t)b * (F_FEAT * H);

    for (int j0 = 0; j0 < F_FEAT * H; j0 += 32) {
        float hv = hb[j0 + lane];
        #pragma unroll
        for (int k = 0; k < 32; k++) {
            float hk = __shfl_sync(0xffffffffu, hv, k);
            acc = fmaf(g_WT[(j0 + k) * H + lane], hk, acc);
        }
    }

    float v = fmaxf(acc, 0.f) * __ldg(W_out + lane);
    #pragma unroll
    for (int off = 16; off; off >>= 1)
        v += __shfl_down_sync(0xffffffffu, v, off);

    if (lane == 0)
        out[b] = fast_sigmoid(v + __ldg(b_out));
}

extern "C" void kernel_launch(void* const* d_in, const int* in_sizes, int n_in,
                              void* d_out, int out_size) {
    const float* input = (const float*)d_in[0];
    const int*   lens  = (const int*)  d_in[1];
    const float* W_ih  = (const float*)d_in[2];
    const float* W_hh  = (const float*)d_in[3];
    const float* b_ih  = (const float*)d_in[4];
    const float* b_hh  = (const float*)d_in[5];
    const float* W_sq  = (const float*)d_in[6];
    const float* b_sq  = (const float*)d_in[7];
    const float* W_out = (const float*)d_in[8];
    const float* b_out = (const float*)d_in[9];
    float* out = (float*)d_out;

    sort_lens<<<(B_TOT + 255) / 256, 256>>>(lens);
    dim3 grid(B_TOT / NB, F_FEAT / 4);
    gru_kernel<<<grid, 128>>>(input, lens, W_ih, W_hh, b_ih, b_hh);
    transpose_wsq<<<(F_FEAT * H * H + 511) / 512, 512>>>(W_sq);
    head_kernel<<<B_TOT / 8, 256>>>(b_sq, W_out, b_out, out);
}

// round 9
// speedup vs baseline: 1.2124x; 1.2124x over previous
#include <cuda_runtime.h>
#include <cuda_bf16.h>

#define F_FEAT 16
#define D_IN   4
#define H      32
#define B_TOT  1024
#define T_MAX  512

typedef unsigned long long ull;

__device__ float g_hT[B_TOT * F_FEAT * H];      // [b][f][h]  == h_cat[b][f*H+h]
__device__ float g_WT[F_FEAT * H * H];          // W_sq transposed
__device__ int   g_perm[B_TOT];                 // batches sorted by len, descending

// HW tanh (MUFU.TANH): 1 op vs EX2+RCP chain. max abs err ~6e-4; GRU gating is
// contractive so end-to-end stays far below the 1e-3 gate (verified by rel_err).
__device__ __forceinline__ float mufu_tanh(float x) {
    float y; asm("tanh.approx.f32 %0, %1;" : "=f"(y) : "f"(x)); return y;
}
__device__ __forceinline__ float fast_sigmoid(float v) {
    return fmaf(0.5f, mufu_tanh(0.5f * v), 0.5f);
}
// exact-ish sigmoid for the single head output (not on any critical path)
__device__ __forceinline__ float precise_sigmoid(float v) {
    return __fdividef(1.f, 1.f + __expf(-v));
}
__device__ __forceinline__ ull pack2(float lo, float hi) {
    ull d; asm("mov.b64 %0, {%1, %2};" : "=l"(d) : "f"(lo), "f"(hi)); return d;
}
__device__ __forceinline__ void unpack2(ull v, float& lo, float& hi) {
    asm("mov.b64 {%0, %1}, %2;" : "=f"(lo), "=f"(hi) : "l"(v));
}
__device__ __forceinline__ ull fma2(ull a, ull b, ull c) {
    ull d; asm("fma.rn.f32x2 %0, %1, %2, %3;" : "=l"(d) : "l"(a), "l"(b), "l"(c)); return d;
}
__device__ __forceinline__ float hsum2(ull v) {
    float lo, hi; unpack2(v, lo, hi); return lo + hi;
}

// Rank-sort batches by length (descending, stable). O(B^2) but tiny (~5us).
__global__ void sort_lens(const int* __restrict__ lens) {
    int b = blockIdx.x * blockDim.x + threadIdx.x;
    if (b >= B_TOT) return;
    int L = lens[b];
    int r = 0;
    for (int j = 0; j < B_TOT; j++) {
        int Lj = __ldg(lens + j);
        r += (Lj < L) || (Lj == L && j < b);
    }
    g_perm[B_TOT - 1 - r] = b;   // descending: longest first
}

// One warp per (feature, batch-PAIR) — the R4 best-known structure.
// 6 independent fma2 chains per step; MUFU.TANH activations shorten the
// per-step serial tail (the part ILP cannot hide).
__global__ void __launch_bounds__(128, 3) gru_kernel(
    const float* __restrict__ input,   // [B, F, T, D]
    const int*   __restrict__ lens,    // [B]
    const float* __restrict__ W_ih,    // [F, 3H, D]
    const float* __restrict__ W_hh,    // [F, 3H, H]
    const float* __restrict__ b_ih,    // [F, 3H]
    const float* __restrict__ b_hh)    // [F, 3H]
{
    __shared__ float hbuf[4][2][2][H];    // [warp][buffer][batch-slot][k]

    const int lane = threadIdx.x & 31;
    const int warp = threadIdx.x >> 5;
    const int pair = blockIdx.x;                 // 0..511, longest pairs first
    const int f    = blockIdx.y * 4 + warp;

    const int b0 = __ldg(g_perm + 2 * pair);         // longer
    const int b1 = __ldg(g_perm + 2 * pair + 1);     // shorter (or equal)
    const int L0 = __ldg(lens + b0);                 // loop bound (max)
    const int L1 = __ldg(lens + b1);

    // --- recurrent weights, packed along k as (W[2q], W[2q+1]) pairs ---
    const float* Whh = W_hh + f * (3 * H) * H;
    ull Wr2[H/2], Wz2[H/2], Wn2[H/2];
    {
        const float4* r4 = (const float4*)(Whh + lane * H);
        const float4* z4 = (const float4*)(Whh + (H + lane) * H);
        const float4* n4 = (const float4*)(Whh + (2 * H + lane) * H);
        #pragma unroll
        for (int q = 0; q < H / 4; q++) {
            float4 a = __ldg(r4 + q);
            Wr2[2*q] = pack2(a.x, a.y);  Wr2[2*q+1] = pack2(a.z, a.w);
            float4 c = __ldg(z4 + q);
            Wz2[2*q] = pack2(c.x, c.y);  Wz2[2*q+1] = pack2(c.z, c.w);
            float4 d = __ldg(n4 + q);
            Wn2[2*q] = pack2(d.x, d.y);  Wn2[2*q+1] = pack2(d.z, d.w);
        }
    }

    // input weights, packed along d
    const float* Wih = W_ih + f * (3 * H) * D_IN;
    const float4 wir = __ldg((const float4*)Wih + lane);
    const float4 wiz = __ldg((const float4*)Wih + H + lane);
    const float4 win = __ldg((const float4*)Wih + 2 * H + lane);
    const ull Wir01 = pack2(wir.x, wir.y), Wir23 = pack2(wir.z, wir.w);
    const ull Wiz01 = pack2(wiz.x, wiz.y), Wiz23 = pack2(wiz.z, wiz.w);
    const ull Win01 = pack2(win.x, win.y), Win23 = pack2(win.z, win.w);

    const float br  = __ldg(b_ih + f * 3 * H + lane)     + __ldg(b_hh + f * 3 * H + lane);
    const float bz  = __ldg(b_ih + f * 3 * H + H + lane) + __ldg(b_hh + f * 3 * H + H + lane);
    const float bin = __ldg(b_ih + f * 3 * H + 2 * H + lane);
    const float bhn = __ldg(b_hh + f * 3 * H + 2 * H + lane);
    const ull  bias_r = pack2(br, 0.f), bias_z = pack2(bz, 0.f);
    const ull  bias_in = pack2(bin, 0.f), bias_hn = pack2(bhn, 0.f);

    const float4* xp0 = (const float4*)input + ((size_t)b0 * F_FEAT + f) * T_MAX;
    const float4* xp1 = (const float4*)input + ((size_t)b1 * F_FEAT + f) * T_MAX;

    float h0 = 0.f, h1 = 0.f;
    hbuf[warp][0][0][lane] = 0.f;
    hbuf[warp][0][1][lane] = 0.f;
    __syncwarp();
    int p = 0;

    float4 x0 = __ldg(xp0);          // L >= 1 always
    float4 x1 = __ldg(xp1);

    for (int t = 0; t < L0; t++) {
        // unconditional clamped prefetch (in-bounds; clamped dup never consumed)
        const int tn = min(t + 1, L0 - 1);
        float4 xn0 = __ldg(xp0 + tn);
        float4 xn1 = __ldg(xp1 + tn);

        // input projections (pair-dots over d), both batches
        const ull xa01 = pack2(x0.x, x0.y), xa23 = pack2(x0.z, x0.w);
        const ull xb01 = pack2(x1.x, x1.y), xb23 = pack2(x1.z, x1.w);
        ull gr2a = fma2(Wir23, xa23, fma2(Wir01, xa01, bias_r));
        ull gz2a = fma2(Wiz23, xa23, fma2(Wiz01, xa01, bias_z));
        ull gn2a = fma2(Win23, xa23, fma2(Win01, xa01, bias_in));
        ull hn2a = bias_hn;
        ull gr2b = fma2(Wir23, xb23, fma2(Wir01, xb01, bias_r));
        ull gz2b = fma2(Wiz23, xb23, fma2(Wiz01, xb01, bias_z));
        ull gn2b = fma2(Win23, xb23, fma2(Win01, xb01, bias_in));
        ull hn2b = bias_hn;

        // recurrent matvecs: 6 independent fma2 chains over k
        const ulonglong2* hpa = (const ulonglong2*)&hbuf[warp][p][0][0];
        const ulonglong2* hpb = (const ulonglong2*)&hbuf[warp][p][1][0];
        #pragma unroll
        for (int q = 0; q < H / 4; q++) {
            ulonglong2 ha = hpa[q];     // LDS.128 broadcast
            ulonglong2 hb = hpb[q];
            gr2a = fma2(Wr2[2*q],   ha.x, gr2a);
            gz2a = fma2(Wz2[2*q],   ha.x, gz2a);
            hn2a = fma2(Wn2[2*q],   ha.x, hn2a);
            gr2b = fma2(Wr2[2*q],   hb.x, gr2b);
            gz2b = fma2(Wz2[2*q],   hb.x, gz2b);
            hn2b = fma2(Wn2[2*q],   hb.x, hn2b);
            gr2a = fma2(Wr2[2*q+1], ha.y, gr2a);
            gz2a = fma2(Wz2[2*q+1], ha.y, gz2a);
            hn2a = fma2(Wn2[2*q+1], ha.y, hn2a);
            gr2b = fma2(Wr2[2*q+1], hb.y, gr2b);
            gz2b = fma2(Wz2[2*q+1], hb.y, gz2b);
            hn2b = fma2(Wn2[2*q+1], hb.y, hn2b);
        }

        // activations via MUFU.TANH: 3 MUFU/batch (was 6) and a ~3x shorter chain
        float ra = fast_sigmoid(hsum2(gr2a));
        float rb = fast_sigmoid(hsum2(gr2b));
        float za = fast_sigmoid(hsum2(gz2a));
        float zb = fast_sigmoid(hsum2(gz2b));
        float na = mufu_tanh(fmaf(ra, hsum2(hn2a), hsum2(gn2a)));
        float nb = mufu_tanh(fmaf(rb, hsum2(hn2b), hsum2(gn2b)));
        h0 = fmaf(za, h0 - na, na);
        float h1n = fmaf(zb, h1 - nb, nb);
        h1 = (t < L1) ? h1n : h1;    // freeze shorter sequence past its length

        hbuf[warp][p ^ 1][0][lane] = h0;
        hbuf[warp][p ^ 1][1][lane] = h1;
        __syncwarp();
        p ^= 1;
        x0 = xn0; x1 = xn1;
    }

    g_hT[((size_t)b0 * F_FEAT + f) * H + lane] = h0;
    g_hT[((size_t)b1 * F_FEAT + f) * H + lane] = h1;
}

// Transpose W_sq [32][512] -> g_WT [512][32]
__global__ void transpose_wsq(const float* __restrict__ W_sq) {
    int i = blockIdx.x * blockDim.x + threadIdx.x;
    if (i < H * F_FEAT * H) {
        int r = i / (F_FEAT * H);
        int j = i % (F_FEAT * H);
        g_WT[j * H + r] = W_sq[i];
    }
}

// One warp per batch: h2 = relu(W_sq @ h_cat + b_sq); out = sigmoid(W_out @ h2 + b_out)
__global__ void head_kernel(
    const float* __restrict__ b_sq,
    const float* __restrict__ W_out,
    const float* __restrict__ b_out,
    float* __restrict__ out)
{
    const int lane = threadIdx.x & 31;
    const int b    = blockIdx.x * (blockDim.x >> 5) + (threadIdx.x >> 5);

    float acc = __ldg(b_sq + lane);
    const float* hb = g_hT + (size_t)b * (F_FEAT * H);

    for (int j0 = 0; j0 < F_FEAT * H; j0 += 32) {
        float hv = hb[j0 + lane];
        #pragma unroll
        for (int k = 0; k < 32; k++) {
            float hk = __shfl_sync(0xffffffffu, hv, k);
            acc = fmaf(g_WT[(j0 + k) * H + lane], hk, acc);
        }
    }

    float v = fmaxf(acc, 0.f) * __ldg(W_out + lane);
    #pragma unroll
    for (int off = 16; off; off >>= 1)
        v += __shfl_down_sync(0xffffffffu, v, off);

    if (lane == 0)
        out[b] = precise_sigmoid(v + __ldg(b_out));
}

extern "C" void kernel_launch(void* const* d_in, const int* in_sizes, int n_in,
                              void* d_out, int out_size) {
    const float* input = (const float*)d_in[0];
    const int*   lens  = (const int*)  d_in[1];
    const float* W_ih  = (const float*)d_in[2];
    const float* W_hh  = (const float*)d_in[3];
    const float* b_ih  = (const float*)d_in[4];
    const float* b_hh  = (const float*)d_in[5];
    const float* W_sq  = (const float*)d_in[6];
    const float* b_sq  = (const float*)d_in[7];
    const float* W_out = (const float*)d_in[8];
    const float* b_out = (const float*)d_in[9];
    float* out = (float*)d_out;

    sort_lens<<<(B_TOT + 255) / 256, 256>>>(lens);
    dim3 grid(B_TOT / 2, F_FEAT / 4);
    gru_kernel<<<grid, 128>>>(input, lens, W_ih, W_hh, b_ih, b_hh);
    transpose_wsq<<<(F_FEAT * H * H + 511) / 512, 512>>>(W_sq);
    head_kernel<<<B_TOT / 8, 256>>>(b_sq, W_out, b_out, out);
}